// round 14
// baseline (speedup 1.0000x reference)
#include <cuda_runtime.h>

#define B_ 32
#define Q_ 16
#define K_ 4096
#define D_ 128
#define V_ 128
#define THREADS 256        /* 8 warps per block, q split 8 ways */
#define NWARP 8
#define GRID 512           /* 512 blocks x 256 keys = 32*4096 */
#define KW 256             /* keys per block */
#define CHUNK 32
#define NCH (KW / CHUNK)
#define QH 2               /* queries per warp */
#define SCALE 0.08838834764831845f  /* 1/sqrt(128) */

// scratch for attn if harness only validates `output`
__device__ float g_attn_scratch[(size_t)B_ * Q_ * K_];

__device__ __forceinline__ void red_add_v4(float* p, float4 v) {
    asm volatile("red.global.add.v4.f32 [%0], {%1,%2,%3,%4};"
                 :: "l"(p), "f"(v.x), "f"(v.y), "f"(v.z), "f"(v.w) : "memory");
}
__device__ __forceinline__ void cp_async16(void* smem_dst, const void* gsrc) {
    unsigned s = (unsigned)__cvta_generic_to_shared(smem_dst);
    asm volatile("cp.async.cg.shared.global [%0], [%1], 16;" :: "r"(s), "l"(gsrc));
}
__device__ __forceinline__ void cp_async_commit() { asm volatile("cp.async.commit_group;"); }
__device__ __forceinline__ void cp_async_wait0() { asm volatile("cp.async.wait_group 0;"); }

__global__ __launch_bounds__(THREADS, 5)
void inv_attn_kernel(const float4* __restrict__ query4,
                     const float4* __restrict__ key4,
                     const float4* __restrict__ value4,
                     float* __restrict__ out,       // [B,Q,V] pre-zeroed, RED-accumulated
                     float* __restrict__ attn_out)  // [B,Q,K]
{
    __shared__ float  att[Q_][CHUNK];       // 2 KB
    __shared__ float4 vt[CHUNK][V_ / 4];    // 16 KB value staging

    const int r    = threadIdx.x >> 5;      // warp role (0..7)
    const int lane = threadIdx.x & 31;
    const int b    = blockIdx.x >> 4;       // 16 blocks per batch
    const int kbase = (blockIdx.x & 15) * KW;

    float4 acc[QH];                          // 8 regs: out rows r*2, r*2+1
    #pragma unroll
    for (int qi = 0; qi < QH; qi++) acc[qi] = make_float4(0.f, 0.f, 0.f, 0.f);

    #pragma unroll 1
    for (int c = 0; c < NCH; c++) {
        const int k0 = kbase + c * CHUNK;

        // ---- stage value rows: warp r loads rows r*4..r*4+3 (under ph1) ----
        const float4* vp =
            value4 + ((size_t)b * K_ + k0 + r * 4) * (V_ / 4) + lane;
        #pragma unroll
        for (int rr = 0; rr < 4; rr++)
            cp_async16(&vt[r * 4 + rr][lane], vp + rr * 32);
        cp_async_commit();

        // ---- ph1: logits for this warp's 2 queries x 32 keys ----
        #pragma unroll 1
        for (int qi = 0; qi < QH; qi++) {
            const int q = r * QH + qi;
            float4 qv = __ldg(query4 + (b * Q_ + q) * (D_ / 4) + lane);
            qv.x *= SCALE; qv.y *= SCALE; qv.z *= SCALE; qv.w *= SCALE;
            const float4* kp =
                key4 + ((size_t)(b * Q_ + q) * K_ + k0) * (D_ / 4);
            #pragma unroll 16
            for (int kk = 0; kk < CHUNK; kk++) {
                float4 kv = __ldcs(kp + kk * 32 + lane);   // 512B coalesced row
                float pv = qv.x * kv.x + qv.y * kv.y + qv.z * kv.z + qv.w * kv.w;
                pv += __shfl_xor_sync(0xffffffffu, pv, 16);
                pv += __shfl_xor_sync(0xffffffffu, pv, 8);
                pv += __shfl_xor_sync(0xffffffffu, pv, 4);
                pv += __shfl_xor_sync(0xffffffffu, pv, 2);
                pv += __shfl_xor_sync(0xffffffffu, pv, 1);
                if (lane == 0) att[q][kk] = pv;
            }
        }
        cp_async_wait0();        // own value rows landed
        __syncthreads();         // logits + all 32 value rows visible

        // ---- ph2: softmax over q; warp r owns keys r*4..r*4+3 ----
        if (lane < 4) {
            const int kk = r * 4 + lane;
            float l[Q_];
            float mx = -1e30f;
            #pragma unroll
            for (int q = 0; q < Q_; q++) { l[q] = att[q][kk]; mx = fmaxf(mx, l[q]); }
            float s = 0.0f;
            #pragma unroll
            for (int q = 0; q < Q_; q++) { l[q] = __expf(l[q] - mx); s += l[q]; }
            float inv = 1.0f / s;
            #pragma unroll
            for (int q = 0; q < Q_; q++) {
                float a = l[q] * inv;
                att[q][kk] = a;
                __stcs(&attn_out[(size_t)(b * Q_ + q) * K_ + k0 + kk], a);
            }
        }
        __syncthreads();

        // ---- ph3: acc[qi] += att[r*2+qi][kk] * vt[kk][lane] ----
        #pragma unroll 4
        for (int kk = 0; kk < CHUNK; kk += 4) {
            float4 v0 = vt[kk + 0][lane];
            float4 v1 = vt[kk + 1][lane];
            float4 v2 = vt[kk + 2][lane];
            float4 v3 = vt[kk + 3][lane];
            #pragma unroll
            for (int qi = 0; qi < QH; qi++) {
                float4 a4 = *reinterpret_cast<const float4*>(&att[r * QH + qi][kk]);
                acc[qi].x += a4.x * v0.x + a4.y * v1.x + a4.z * v2.x + a4.w * v3.x;
                acc[qi].y += a4.x * v0.y + a4.y * v1.y + a4.z * v2.y + a4.w * v3.y;
                acc[qi].z += a4.x * v0.z + a4.y * v1.z + a4.z * v2.z + a4.w * v3.z;
                acc[qi].w += a4.x * v0.w + a4.y * v1.w + a4.z * v2.w + a4.w * v3.w;
            }
        }
        __syncthreads();   // att + vt reused next chunk
    }

    // ---- flush: one RED.v4 per owned q per lane ----
    float* o = out + ((size_t)b * Q_ + r * QH) * V_ + lane * 4;
    #pragma unroll
    for (int qi = 0; qi < QH; qi++)
        red_add_v4(o + (size_t)qi * V_, acc[qi]);
}

extern "C" void kernel_launch(void* const* d_in, const int* in_sizes, int n_in,
                              void* d_out, int out_size)
{
    const float4* query = (const float4*)d_in[0];
    const float4* key   = (const float4*)d_in[1];
    const float4* value = (const float4*)d_in[2];

    float* out = (float*)d_out;
    float* attn;
    const int out_elems  = B_ * Q_ * V_;        // 65536
    const int attn_elems = B_ * Q_ * K_;        // 2097152

    if (out_size >= out_elems + attn_elems) {
        attn = out + out_elems;                 // (output, attn) concatenated
    } else {
        cudaGetSymbolAddress((void**)&attn, g_attn_scratch);
    }

    cudaMemsetAsync(d_out, 0, (size_t)out_elems * sizeof(float));

    inv_attn_kernel<<<GRID, THREADS>>>(query, key, value, out, attn);
}

// round 15
// speedup vs baseline: 1.1021x; 1.1021x over previous
#include <cuda_runtime.h>

#define B_ 32
#define Q_ 16
#define K_ 4096
#define D_ 128
#define V_ 128
#define THREADS 128        /* 4 warps per block, q split 4 ways */
#define NWARP 4
#define GRID 1024          /* 1024 blocks x 128 keys = 32*4096 */
#define KW 128             /* keys per block */
#define CHUNK 16
#define NCH (KW / CHUNK)
#define QH 4               /* queries per warp */
#define ATP 20             /* padded att row (floats), 16B aligned */
#define SCALE 0.08838834764831845f  /* 1/sqrt(128) */

// scratch for attn if harness only validates `output`
__device__ float g_attn_scratch[(size_t)B_ * Q_ * K_];

__device__ __forceinline__ void red_add_v4(float* p, float4 v) {
    asm volatile("red.global.add.v4.f32 [%0], {%1,%2,%3,%4};"
                 :: "l"(p), "f"(v.x), "f"(v.y), "f"(v.z), "f"(v.w) : "memory");
}
__device__ __forceinline__ void cp_async16(void* smem_dst, const void* gsrc) {
    unsigned s = (unsigned)__cvta_generic_to_shared(smem_dst);
    asm volatile("cp.async.cg.shared.global [%0], [%1], 16;" :: "r"(s), "l"(gsrc));
}
__device__ __forceinline__ void cp_async_commit() { asm volatile("cp.async.commit_group;"); }
__device__ __forceinline__ void cp_async_wait0() { asm volatile("cp.async.wait_group 0;"); }
__device__ __forceinline__ void cp_async_wait1() { asm volatile("cp.async.wait_group 1;"); }

__global__ __launch_bounds__(THREADS, 8)
void inv_attn_kernel(const float4* __restrict__ query4,
                     const float4* __restrict__ key4,
                     const float4* __restrict__ value4,
                     float* __restrict__ out,       // [B,Q,V] pre-zeroed, RED-accumulated
                     float* __restrict__ attn_out)  // [B,Q,K]
{
    __shared__ float  att[2][Q_][ATP];      // 2.5 KB, parity-buffered
    __shared__ float4 vt[2][CHUNK][V_ / 4]; // 16 KB, parity-buffered value tiles

    const int r    = threadIdx.x >> 5;      // warp role (0..3)
    const int lane = threadIdx.x & 31;
    const int b    = blockIdx.x >> 5;       // 32 blocks per batch
    const int kbase = (blockIdx.x & 31) * KW;

    float4 acc[QH];                          // 16 regs: out rows r*4..r*4+3
    #pragma unroll
    for (int qi = 0; qi < QH; qi++) acc[qi] = make_float4(0.f, 0.f, 0.f, 0.f);

    // ---- prologue: stage value tile of chunk 0 ----
    {
        const float4* vp =
            value4 + ((size_t)b * K_ + kbase + r * 4) * (V_ / 4) + lane;
        #pragma unroll
        for (int rr = 0; rr < 4; rr++)
            cp_async16(&vt[0][r * 4 + rr][lane], vp + rr * 32);
        cp_async_commit();
    }

    #pragma unroll 1
    for (int c = 0; c < NCH; c++) {
        const int k0 = kbase + c * CHUNK;
        const int p  = c & 1;

        // ---- ph1: logits for this warp's 4 queries x 16 keys ----
        #pragma unroll 1
        for (int qi = 0; qi < QH; qi++) {
            const int q = r * QH + qi;
            float4 qv = __ldg(query4 + (b * Q_ + q) * (D_ / 4) + lane);
            qv.x *= SCALE; qv.y *= SCALE; qv.z *= SCALE; qv.w *= SCALE;
            const float4* kp =
                key4 + ((size_t)(b * Q_ + q) * K_ + k0) * (D_ / 4);
            #pragma unroll
            for (int kk = 0; kk < CHUNK; kk++) {
                float4 kv = __ldcs(kp + kk * 32 + lane);   // 512B coalesced row
                float pv = qv.x * kv.x + qv.y * kv.y + qv.z * kv.z + qv.w * kv.w;
                pv += __shfl_xor_sync(0xffffffffu, pv, 16);
                pv += __shfl_xor_sync(0xffffffffu, pv, 8);
                pv += __shfl_xor_sync(0xffffffffu, pv, 4);
                pv += __shfl_xor_sync(0xffffffffu, pv, 2);
                pv += __shfl_xor_sync(0xffffffffu, pv, 1);
                if (lane == 0) att[p][q][kk] = pv;
            }
        }
        __syncthreads();    // all logits of chunk c visible

        // ---- ph2: parallel softmax over q.
        // 16 lanes: kl = lane>>2 -> key r*4+kl; qg = lane&3 -> queries qg*4..+3.
        if (lane < 16) {
            const int kk = r * 4 + (lane >> 2);
            const int qg = lane & 3;
            float l0 = att[p][qg * 4 + 0][kk];
            float l1 = att[p][qg * 4 + 1][kk];
            float l2 = att[p][qg * 4 + 2][kk];
            float l3 = att[p][qg * 4 + 3][kk];
            float mx = fmaxf(fmaxf(l0, l1), fmaxf(l2, l3));
            mx = fmaxf(mx, __shfl_xor_sync(0xffffu, mx, 1));
            mx = fmaxf(mx, __shfl_xor_sync(0xffffu, mx, 2));
            l0 = __expf(l0 - mx); l1 = __expf(l1 - mx);
            l2 = __expf(l2 - mx); l3 = __expf(l3 - mx);
            float s = l0 + l1 + l2 + l3;
            s += __shfl_xor_sync(0xffffu, s, 1);
            s += __shfl_xor_sync(0xffffu, s, 2);
            float inv = 1.0f / s;
            l0 *= inv; l1 *= inv; l2 *= inv; l3 *= inv;
            att[p][qg * 4 + 0][kk] = l0;
            att[p][qg * 4 + 1][kk] = l1;
            att[p][qg * 4 + 2][kk] = l2;
            att[p][qg * 4 + 3][kk] = l3;
            float* ao = attn_out + ((size_t)(b * Q_ + qg * 4) * K_) + k0 + kk;
            __stcs(ao,            l0);
            __stcs(ao + K_,       l1);
            __stcs(ao + 2ul * K_, l2);
            __stcs(ao + 3ul * K_, l3);
        }

        // ---- stage next chunk's value tile (opposite parity) ----
        if (c + 1 < NCH) {
            const float4* vp =
                value4 + ((size_t)b * K_ + k0 + CHUNK + r * 4) * (V_ / 4) + lane;
            #pragma unroll
            for (int rr = 0; rr < 4; rr++)
                cp_async16(&vt[p ^ 1][r * 4 + rr][lane], vp + rr * 32);
            cp_async_commit();
            cp_async_wait1();    // this chunk's tile complete, next in flight
        } else {
            cp_async_wait0();
        }
        __syncthreads();    // softmax results + everyone's vt[p] rows visible

        // ---- ph3: acc[qi] += att[r*4+qi][kk] * vt[kk][lane] ----
        #pragma unroll 4
        for (int kk = 0; kk < CHUNK; kk += 4) {
            float4 v0 = vt[p][kk + 0][lane];
            float4 v1 = vt[p][kk + 1][lane];
            float4 v2 = vt[p][kk + 2][lane];
            float4 v3 = vt[p][kk + 3][lane];
            #pragma unroll
            for (int qi = 0; qi < QH; qi++) {
                float4 a4 = *reinterpret_cast<const float4*>(&att[p][r * QH + qi][kk]);
                acc[qi].x += a4.x * v0.x + a4.y * v1.x + a4.z * v2.x + a4.w * v3.x;
                acc[qi].y += a4.x * v0.y + a4.y * v1.y + a4.z * v2.y + a4.w * v3.y;
                acc[qi].z += a4.x * v0.z + a4.y * v1.z + a4.z * v2.z + a4.w * v3.z;
                acc[qi].w += a4.x * v0.w + a4.y * v1.w + a4.z * v2.w + a4.w * v3.w;
            }
        }
        // no third barrier: next chunk uses opposite-parity att/vt buffers
    }

    // ---- flush: one RED.v4 per owned q per lane ----
    float* o = out + ((size_t)b * Q_ + r * QH) * V_ + lane * 4;
    #pragma unroll
    for (int qi = 0; qi < QH; qi++)
        red_add_v4(o + (size_t)qi * V_, acc[qi]);
}

extern "C" void kernel_launch(void* const* d_in, const int* in_sizes, int n_in,
                              void* d_out, int out_size)
{
    const float4* query = (const float4*)d_in[0];
    const float4* key   = (const float4*)d_in[1];
    const float4* value = (const float4*)d_in[2];

    float* out = (float*)d_out;
    float* attn;
    const int out_elems  = B_ * Q_ * V_;        // 65536
    const int attn_elems = B_ * Q_ * K_;        // 2097152

    if (out_size >= out_elems + attn_elems) {
        attn = out + out_elems;                 // (output, attn) concatenated
    } else {
        cudaGetSymbolAddress((void**)&attn, g_attn_scratch);
    }

    cudaMemsetAsync(d_out, 0, (size_t)out_elems * sizeof(float));

    inv_attn_kernel<<<GRID, THREADS>>>(query, key, value, out, attn);
}